// round 10
// baseline (speedup 1.0000x reference)
#include <cuda_runtime.h>
#include <cuda_fp16.h>
#include <cstdint>
#include <math.h>

#define TOKS 512
#define HDIM 1024
#define FDIM 4096
#define NEXP 8
#define SLOT 512
#define KSPLIT 4
#define RS 40                        // halves per smem row (80 B, conflict-free)
#define A_STG (128 * RS)             // 5120 halves = 10240 B per A stage
#define B1STG (128 * RS)             // gemm1 B stage (w1 rows 0-63, w3 rows 64-127)
#define B2STG (64 * RS)              // gemm2 B stage

__device__ __half d_xh[TOKS * HDIM];
__device__ __half d_h[NEXP * SLOT * FDIM];
__device__ float  d_po[KSPLIT * NEXP * SLOT * HDIM];
__device__ int    d_count[NEXP];
__device__ int    d_tok[NEXP * SLOT];
__device__ float  d_mult[NEXP * SLOT];
__device__ int    d_pidx[TOKS * 2];

// ---------------- helpers ----------------------------------------------------
__device__ __forceinline__ unsigned pk2(float a, float b) {
    __half2 h = __floats2half2_rn(a, b); return *(unsigned*)&h;
}
__device__ __forceinline__ void mma16(float* c, const unsigned* a, const unsigned* b) {
    asm volatile("mma.sync.aligned.m16n8k16.row.col.f32.f16.f16.f32 "
        "{%0,%1,%2,%3}, {%4,%5,%6,%7}, {%8,%9}, {%0,%1,%2,%3};"
        : "+f"(c[0]), "+f"(c[1]), "+f"(c[2]), "+f"(c[3])
        : "r"(a[0]), "r"(a[1]), "r"(a[2]), "r"(a[3]), "r"(b[0]), "r"(b[1]));
}
__device__ __forceinline__ void ldsm4(unsigned* r, unsigned addr) {
    asm volatile("ldmatrix.sync.aligned.m8n8.x4.shared.b16 {%0,%1,%2,%3}, [%4];"
        : "=r"(r[0]), "=r"(r[1]), "=r"(r[2]), "=r"(r[3]) : "r"(addr));
}
__device__ __forceinline__ void cpa(unsigned dst, const void* src) {
    asm volatile("cp.async.cg.shared.global [%0], [%1], 16;" :: "r"(dst), "l"(src));
}
#define CP_COMMIT asm volatile("cp.async.commit_group;")
#define CP_WAIT2  asm volatile("cp.async.wait_group 2;")

// ---------------- small kernels ----------------------------------------------
__global__ void init_kernel() { if (threadIdx.x < NEXP) d_count[threadIdx.x] = 0; }
__global__ void convx_kernel(const float* __restrict__ x) {
    int i = (blockIdx.x * 256 + threadIdx.x) * 4;
    float4 v = *(const float4*)(x + i);
    uint2 o; o.x = pk2(v.x, v.y); o.y = pk2(v.z, v.w);
    *(uint2*)&d_xh[i] = o;
}
__global__ void routing_kernel(const float* __restrict__ x, const float* __restrict__ gw) {
    int t = blockIdx.x, tid = threadIdx.x, w = tid >> 5, lane = tid & 31;
    __shared__ float lg[NEXP];
    const float* xr = x + (size_t)t * HDIM;
    const float* gr = gw + (size_t)w * HDIM;
    float s = 0.f;
    for (int i = lane * 4; i < HDIM; i += 128) {
        float4 a = *(const float4*)(xr + i);
        float4 b = *(const float4*)(gr + i);
        s += a.x * b.x + a.y * b.y + a.z * b.z + a.w * b.w;
    }
    #pragma unroll
    for (int o = 16; o; o >>= 1) s += __shfl_xor_sync(0xFFFFFFFFu, s, o);
    if (lane == 0) lg[w] = s;
    __syncthreads();
    if (tid == 0) {
        float l[NEXP];
        #pragma unroll
        for (int e = 0; e < NEXP; e++) l[e] = lg[e];
        int s1 = 0;
        for (int e = 1; e < NEXP; e++) if (l[e] > l[s1]) s1 = e;
        float m1 = l[s1];
        int s2 = (s1 == 0) ? 1 : 0;
        for (int e = 0; e < NEXP; e++) { if (e == s1) continue; if (l[e] > l[s2]) s2 = e; }
        float m2 = l[s2];
        float mult1, mult2;
        {
            float keep[NEXP]; float mx = -1e30f;
            for (int e = 0; e < NEXP; e++) {
                float f = fmaxf(fabsf(l[e]), m1);
                keep[e] = ((m1 - l[e]) / f > 0.02f) ? -1e30f : l[e];
                mx = fmaxf(mx, keep[e]);
            }
            float sum = 0.f, num = 0.f;
            for (int e = 0; e < NEXP; e++) {
                float p = (keep[e] <= -1e30f) ? 0.f : expf(keep[e] - mx);
                sum += p; if (e == s1) num = p;
            }
            mult1 = num / sum;
        }
        {
            float keep[NEXP]; float mx = -1e30f;
            for (int e = 0; e < NEXP; e++) {
                float f = fmaxf(fabsf(l[e]), m2);
                bool msk = ((m2 - l[e]) / f > 0.02f) || (e == s1);
                keep[e] = msk ? -1e30f : l[e];
                mx = fmaxf(mx, keep[e]);
            }
            float sum = 0.f, num = 0.f;
            for (int e = 0; e < NEXP; e++) {
                float p = (keep[e] <= -1e30f) ? 0.f : expf(keep[e] - mx);
                sum += p; if (e == s2) num = p;
            }
            mult2 = num / sum;
        }
        int p = atomicAdd(&d_count[s1], 1);
        d_tok[s1 * SLOT + p] = t; d_mult[s1 * SLOT + p] = mult1;
        d_pidx[t * 2 + 0] = s1 * SLOT + p;
        p = atomicAdd(&d_count[s2], 1);
        d_tok[s2 * SLOT + p] = t; d_mult[s2 * SLOT + p] = mult2;
        d_pidx[t * 2 + 1] = s2 * SLOT + p;
    }
}

// ---------------- GEMM1: 128x64 fused w1/w3, fp16 smem, warps 4x2 ------------
// smem: A ring-4 (4 x 10240 B) + B double-buffer (2 x 10240 B) = 61440 B
__global__ __launch_bounds__(256, 2) void gemm1_kernel(const float* __restrict__ w1,
                                                       const float* __restrict__ w3) {
    extern __shared__ __half smh[];
    __half* Ab = smh;                 // 4 * A_STG
    __half* Bb = smh + 4 * A_STG;     // 2 * B1STG

    int e = blockIdx.y >> 2, mtile = blockIdx.y & 3;
    int cnt = d_count[e];
    int m0 = mtile * 128;
    if (m0 >= cnt) return;
    int n0 = blockIdx.x * 64;
    int tid = threadIdx.x;

    // A fill: 2 x 16B chunks/thread, 128 rows x 4 chunks
    const __half* aptr[2]; unsigned aoffs[2];
    #pragma unroll
    for (int j = 0; j < 2; j++) {
        int gidx = tid + 256 * j;
        int row = gidx >> 2, c = gidx & 3;
        int rr = m0 + row; if (rr >= cnt) rr = cnt - 1;
        aptr[j]  = d_xh + (size_t)d_tok[e * SLOT + rr] * HDIM + c * 8;
        aoffs[j] = (unsigned)(row * RS + c * 8) * 2;
    }
    // B fill: row = tid>>1 (0..127; <64 = w1, >=64 = w3), half = tid&1 (16 floats)
    int brow = tid >> 1, bhalf = tid & 1;
    const float* bsrc = (brow < 64)
        ? w1 + ((size_t)e * FDIM + n0 + brow) * HDIM + bhalf * 16
        : w3 + ((size_t)e * FDIM + n0 + brow - 64) * HDIM + bhalf * 16;
    unsigned bsts = (unsigned)(brow * RS + bhalf * 16) * 2;   // bytes

    unsigned uA = (unsigned)__cvta_generic_to_shared(Ab);
    const int NKT = HDIM / 32;   // 32

    #pragma unroll
    for (int s = 0; s < 2; s++) {
        cpa(uA + (unsigned)s * (A_STG * 2) + aoffs[0], aptr[0] + s * 32);
        cpa(uA + (unsigned)s * (A_STG * 2) + aoffs[1], aptr[1] + s * 32);
        CP_COMMIT;
    }
    float4 r[4];
    #pragma unroll
    for (int j = 0; j < 4; j++) r[j] = *(const float4*)(bsrc + j * 4);

    int warp = tid >> 5, lane = tid & 31;
    int wm = warp >> 1, wn = warp & 1;   // 4 x 2, warp tile 32x32 (per matrix)
    int g = lane >> 2, tg = lane & 3;

    unsigned aoffm[2];
    #pragma unroll
    for (int mi = 0; mi < 2; mi++)
        aoffm[mi] = (unsigned)((wm * 32 + mi * 16 + (lane & 7) + ((lane >> 3) & 1) * 8) * RS
                               + (lane >> 4) * 8) * 2;

    float acc1[2][4][4] = {}, acc3[2][4][4] = {};

    for (int kt = 0; kt < NKT; kt++) {
        // store B(kt) fp16 into buf kt&1 (prev readers of this buf done: sync(kt-1))
        char* bbuf = (char*)Bb + (kt & 1) * (B1STG * 2);
        uint4 u0, u1;
        u0.x = pk2(r[0].x, r[0].y); u0.y = pk2(r[0].z, r[0].w);
        u0.z = pk2(r[1].x, r[1].y); u0.w = pk2(r[1].z, r[1].w);
        u1.x = pk2(r[2].x, r[2].y); u1.y = pk2(r[2].z, r[2].w);
        u1.z = pk2(r[3].x, r[3].y); u1.w = pk2(r[3].z, r[3].w);
        *(uint4*)(bbuf + bsts) = u0;
        *(uint4*)(bbuf + bsts + 16) = u1;
        if (kt + 1 < NKT) {
            #pragma unroll
            for (int j = 0; j < 4; j++) r[j] = *(const float4*)(bsrc + (kt + 1) * 32 + j * 4);
        }
        if (kt + 2 < NKT) {
            unsigned so = (unsigned)((kt + 2) & 3) * (A_STG * 2);
            cpa(uA + so + aoffs[0], aptr[0] + (kt + 2) * 32);
            cpa(uA + so + aoffs[1], aptr[1] + (kt + 2) * 32);
        }
        CP_COMMIT;
        CP_WAIT2;
        __syncthreads();

        unsigned sAc = uA + (unsigned)(kt & 3) * (A_STG * 2);
        const __half* Bc = Bb + (kt & 1) * B1STG;

        #pragma unroll
        for (int ks = 0; ks < 2; ks++) {
            unsigned af[2][4];
            ldsm4(af[0], sAc + aoffm[0] + ks * 32);
            ldsm4(af[1], sAc + aoffm[1] + ks * 32);
            int k0 = ks * 16 + 2 * tg;
            #pragma unroll
            for (int ni = 0; ni < 4; ni++) {
                int rb = (wn * 32 + ni * 8 + g) * RS + k0;
                unsigned br1[2], br3[2];
                br1[0] = *(const unsigned*)(Bc + rb);
                br1[1] = *(const unsigned*)(Bc + rb + 8);
                br3[0] = *(const unsigned*)(Bc + rb + 64 * RS);
                br3[1] = *(const unsigned*)(Bc + rb + 64 * RS + 8);
                #pragma unroll
                for (int mi = 0; mi < 2; mi++) {
                    mma16(acc1[mi][ni], af[mi], br1);
                    mma16(acc3[mi][ni], af[mi], br3);
                }
            }
        }
        __syncthreads();
    }

    // epilogue: silu(s1)*s3 -> d_h fp16
    #pragma unroll
    for (int mi = 0; mi < 2; mi++)
    #pragma unroll
    for (int ni = 0; ni < 4; ni++)
    #pragma unroll
    for (int h = 0; h < 2; h++) {
        int lr = wm * 32 + mi * 16 + g + h * 8;
        if (m0 + lr < cnt) {
            int col = n0 + wn * 32 + ni * 8 + tg * 2;
            float v1a = acc1[mi][ni][h * 2], v1b = acc1[mi][ni][h * 2 + 1];
            float v3a = acc3[mi][ni][h * 2], v3b = acc3[mi][ni][h * 2 + 1];
            float h0 = v1a * v3a / (1.f + __expf(-v1a));
            float h1 = v1b * v3b / (1.f + __expf(-v1b));
            *(unsigned*)&d_h[((size_t)(e * SLOT + m0 + lr)) * FDIM + col] = pk2(h0, h1);
        }
    }
}

// ---------------- GEMM2: 128x64, split-K x4, fp16 smem, warps 4x2 ------------
// smem: A ring-4 (40960 B) + B double-buffer (2 x 5120 B) = 51200 B
__global__ __launch_bounds__(256, 3) void gemm2_kernel(const float* __restrict__ w2) {
    extern __shared__ __half smh[];
    __half* Ab = smh;
    __half* Bb = smh + 4 * A_STG;

    int e = blockIdx.y >> 2, mtile = blockIdx.y & 3;
    int cnt = d_count[e];
    int m0 = mtile * 128;
    if (m0 >= cnt) return;
    int n0 = blockIdx.x * 64;
    int kz = blockIdx.z;
    int kbase = kz * (FDIM / KSPLIT);
    int tid = threadIdx.x;

    const __half* aptr[2]; unsigned aoffs[2];
    #pragma unroll
    for (int j = 0; j < 2; j++) {
        int gidx = tid + 256 * j;
        int row = gidx >> 2, c = gidx & 3;
        int rr = m0 + row; if (rr >= cnt) rr = cnt - 1;
        aptr[j]  = d_h + ((size_t)(e * SLOT) + rr) * FDIM + kbase + c * 8;
        aoffs[j] = (unsigned)(row * RS + c * 8) * 2;
    }
    // B fill: row = tid>>2 (0..63), quarter = tid&3 (8 floats)
    int brow = tid >> 2, bq4 = tid & 3;
    const float* bsrc = w2 + ((size_t)e * HDIM + n0 + brow) * FDIM + kbase + bq4 * 8;
    unsigned bsts = (unsigned)(brow * RS + bq4 * 8) * 2;

    unsigned uA = (unsigned)__cvta_generic_to_shared(Ab);
    const int NKT = (FDIM / KSPLIT) / 32;   // 32

    #pragma unroll
    for (int s = 0; s < 2; s++) {
        cpa(uA + (unsigned)s * (A_STG * 2) + aoffs[0], aptr[0] + s * 32);
        cpa(uA + (unsigned)s * (A_STG * 2) + aoffs[1], aptr[1] + s * 32);
        CP_COMMIT;
    }
    float4 r[2];
    r[0] = *(const float4*)bsrc; r[1] = *(const float4*)(bsrc + 4);

    int warp = tid >> 5, lane = tid & 31;
    int wm = warp >> 1, wn = warp & 1;
    int g = lane >> 2, tg = lane & 3;

    unsigned aoffm[2];
    #pragma unroll
    for (int mi = 0; mi < 2; mi++)
        aoffm[mi] = (unsigned)((wm * 32 + mi * 16 + (lane & 7) + ((lane >> 3) & 1) * 8) * RS
                               + (lane >> 4) * 8) * 2;

    float acc[2][4][4] = {};

    for (int kt = 0; kt < NKT; kt++) {
        char* bbuf = (char*)Bb + (kt & 1) * (B2STG * 2);
        uint4 u0;
        u0.x = pk2(r[0].x, r[0].y); u0.y = pk2(r[0].z, r[0].w);
        u0.z = pk2(r[1].x, r[1].y); u0.w = pk2(r[1].z, r[1].w);
        *(uint4*)(bbuf + bsts) = u0;
        if (kt + 1 < NKT) {
            r[0] = *(const float4*)(bsrc + (kt + 1) * 32);
            r[1] = *(const float4*)(bsrc + (kt + 1) * 32 + 4);
        }
        if (kt + 2 < NKT) {
            unsigned so = (unsigned)((kt + 2) & 3) * (A_STG * 2);
            cpa(uA + so + aoffs[0], aptr[0] + (kt + 2) * 32);
            cpa(uA + so + aoffs[1], aptr[1] + (kt + 2) * 32);
        }
        CP_COMMIT;
        CP_WAIT2;
        __syncthreads();

        unsigned sAc = uA + (unsigned)(kt & 3) * (A_STG * 2);
        const __half* Bc = Bb + (kt & 1) * B2STG;

        #pragma unroll
        for (int ks = 0; ks < 2; ks++) {
            unsigned af[2][4];
            ldsm4(af[0], sAc + aoffm[0] + ks * 32);
            ldsm4(af[1], sAc + aoffm[1] + ks * 32);
            int k0 = ks * 16 + 2 * tg;
            #pragma unroll
            for (int ni = 0; ni < 4; ni++) {
                int rb = (wn * 32 + ni * 8 + g) * RS + k0;
                unsigned br[2];
                br[0] = *(const unsigned*)(Bc + rb);
                br[1] = *(const unsigned*)(Bc + rb + 8);
                #pragma unroll
                for (int mi = 0; mi < 2; mi++) mma16(acc[mi][ni], af[mi], br);
            }
        }
        __syncthreads();
    }

    float* po = d_po + (size_t)kz * (NEXP * SLOT * HDIM);
    #pragma unroll
    for (int mi = 0; mi < 2; mi++)
    #pragma unroll
    for (int ni = 0; ni < 4; ni++)
    #pragma unroll
    for (int h = 0; h < 2; h++) {
        int lr = wm * 32 + mi * 16 + g + h * 8;
        if (m0 + lr < cnt) {
            float mult = d_mult[e * SLOT + m0 + lr];
            int col = n0 + wn * 32 + ni * 8 + tg * 2;
            float2 o;
            o.x = acc[mi][ni][h * 2]     * mult;
            o.y = acc[mi][ni][h * 2 + 1] * mult;
            *(float2*)&po[((size_t)(e * SLOT + m0 + lr)) * HDIM + col] = o;
        }
    }
}

// ---------------- finalize ---------------------------------------------------
__global__ void finalize_kernel(float* __restrict__ out) {
    int t = blockIdx.x, i = threadIdx.x;
    int p0 = d_pidx[t * 2], p1 = d_pidx[t * 2 + 1];
    float4 o = make_float4(0.f, 0.f, 0.f, 0.f);
    #pragma unroll
    for (int kz = 0; kz < KSPLIT; kz++) {
        const float* po = d_po + (size_t)kz * (NEXP * SLOT * HDIM);
        float4 a = ((const float4*)(po + (size_t)p0 * HDIM))[i];
        float4 b = ((const float4*)(po + (size_t)p1 * HDIM))[i];
        o.x += a.x + b.x; o.y += a.y + b.y;
        o.z += a.z + b.z; o.w += a.w + b.w;
    }
    ((float4*)(out + (size_t)t * HDIM))[i] = o;
}

// ---------------- launch ----------------------------------------------------
extern "C" void kernel_launch(void* const* d_in, const int* in_sizes, int n_in,
                              void* d_out, int out_size) {
    const float* x  = (const float*)d_in[0];
    const float* gw = (const float*)d_in[1];
    const float* w1 = (const float*)d_in[2];
    const float* w2 = (const float*)d_in[3];
    const float* w3 = (const float*)d_in[4];
    float* out = (float*)d_out;

    const int smem1 = (4 * A_STG + 2 * B1STG) * 2;   // 61440 B
    const int smem2 = (4 * A_STG + 2 * B2STG) * 2;   // 51200 B
    cudaFuncSetAttribute(gemm1_kernel, cudaFuncAttributeMaxDynamicSharedMemorySize, smem1);
    cudaFuncSetAttribute(gemm2_kernel, cudaFuncAttributeMaxDynamicSharedMemorySize, smem2);

    init_kernel<<<1, 32>>>();
    convx_kernel<<<TOKS * HDIM / 1024, 256>>>(x);
    routing_kernel<<<TOKS, 256>>>(x, gw);
    gemm1_kernel<<<dim3(FDIM / 64, NEXP * 4), 256, smem1>>>(w1, w3);
    gemm2_kernel<<<dim3(HDIM / 64, NEXP * 4, KSPLIT), 256, smem2>>>(w2);
    finalize_kernel<<<TOKS, 256>>>(out);
}